// round 1
// baseline (speedup 1.0000x reference)
#include <cuda_runtime.h>
#include <float.h>

// Fused MaxPool(2x2,s1,SAME-after) -> depthwise binomial 3x3 blur (zero pad)
// -> AvgPool(2x2,s2,VALID). Algebra: blur*avg collapse to a separable 4x4
// stencil with per-dim weights (1,3,3,1)/8, stride 2, applied to the maxpool
// output y. y is computed on the fly from x via column pair-maxes.
//
// x: (32,112,112,128) f32 NHWC, out: (32,56,56,128) f32.
// float4 over channels: 32 lanes cover C=128. One warp handles one tile's
// channel dim -> every global load is a contiguous 512B warp transaction.

#define TILE_R 2                 // output rows per thread
#define TILE_W 4                 // output cols per thread
#define NY     (2*TILE_R + 2)    // y rows needed   = 6
#define NXROWS (2*TILE_R + 3)    // x rows loaded   = 7
#define NT     (2*TILE_W + 3)    // x column steps  = 11
#define TI_N   (56 / TILE_R)     // 28 row tiles
#define TJ_N   (56 / TILE_W)     // 14 col tiles

__device__ __forceinline__ float4 f4max(float4 a, float4 b) {
    return make_float4(fmaxf(a.x,b.x), fmaxf(a.y,b.y),
                       fmaxf(a.z,b.z), fmaxf(a.w,b.w));
}
__device__ __forceinline__ void f4fma(float4& acc, float w, float4 v) {
    acc.x = fmaf(w, v.x, acc.x);
    acc.y = fmaf(w, v.y, acc.y);
    acc.z = fmaf(w, v.z, acc.z);
    acc.w = fmaf(w, v.w, acc.w);
}

__global__ void __launch_bounds__(256, 1)
mbp_kernel(const float4* __restrict__ x, float4* __restrict__ out) {
    const int lane = threadIdx.x;                         // channel vec 0..31
    const int tile = blockIdx.x * blockDim.y + threadIdx.y;
    if (tile >= 32 * TI_N * TJ_N) return;

    const int tj = tile % TJ_N;
    const int t2 = tile / TJ_N;
    const int ti = t2 % TI_N;
    const int b  = t2 / TI_N;

    const int oi0 = ti * TILE_R;        // first output row
    const int oj0 = tj * TILE_W;        // first output col
    const int xr0 = 2*oi0 - 1;          // first x row of patch
    const int xc0 = 2*oj0 - 1;          // first x col of patch

    const float4 NEG = make_float4(-FLT_MAX, -FLT_MAX, -FLT_MAX, -FLT_MAX);
    const float4 ZERO = make_float4(0.f, 0.f, 0.f, 0.f);

    const float4* xb = x + ((size_t)b * 112 * 112) * 32 + lane;

    const float4* rowPtr[NXROWS];
    bool rowOk[NXROWS];
#pragma unroll
    for (int k = 0; k < NXROWS; k++) {
        int gr = xr0 + k;
        rowOk[k] = (gr >= 0) && (gr < 112);
        rowPtr[k] = xb + (long long)(gr * 112) * 32;   // never deref if !rowOk
    }

    const bool topZero   = (ti == 0);          // y row -1  -> 0 (blur zero pad)
    const bool botZero   = (ti == TI_N - 1);   // y row 112 -> 0
    const bool leftSkip  = (tj == 0);          // y col -1  -> skip
    const bool rightSkip = (tj == TJ_N - 1);   // y col 112 -> skip

    const float wv0 = 0.125f, wv1 = 0.375f;    // (1,3,3,1)/8

    float4 acc[TILE_R][TILE_W];
#pragma unroll
    for (int r = 0; r < TILE_R; r++)
#pragma unroll
        for (int w = 0; w < TILE_W; w++) acc[r][w] = ZERO;

    // Prime: column pair-maxes (cm[k] = max over x rows k,k+1) at x col xc0.
    float4 cmPrev[NY];
    {
        const int gc = xc0;
        const bool colOk = (gc >= 0);          // gc < 112 always at t=0
        float4 xv[NXROWS];
#pragma unroll
        for (int k = 0; k < NXROWS; k++)
            xv[k] = (colOk && rowOk[k]) ? __ldg(rowPtr[k] + (size_t)gc * 32) : NEG;
#pragma unroll
        for (int k = 0; k < NY; k++) cmPrev[k] = f4max(xv[k], xv[k+1]);
    }

    // Slide across x columns; each step finalizes one y column.
#pragma unroll
    for (int t = 1; t < NT; t++) {
        const int gc = xc0 + t;                // >= 0 for t>=1
        const bool colOk = (gc < 112);
        float4 xv[NXROWS];
#pragma unroll
        for (int k = 0; k < NXROWS; k++)
            xv[k] = (colOk && rowOk[k]) ? __ldg(rowPtr[k] + (size_t)gc * 32) : NEG;

        float4 cm[NY];
#pragma unroll
        for (int k = 0; k < NY; k++) cm[k] = f4max(xv[k], xv[k+1]);

        // y column jy = xc0 + t - 1 ; skip if outside [0,112)
        const bool ySkip = (t == 1 && leftSkip) || (t == NT-1 && rightSkip);
        if (!ySkip) {
            float4 yc[NY];
#pragma unroll
            for (int k = 0; k < NY; k++) yc[k] = f4max(cmPrev[k], cm[k]);
            if (topZero) yc[0]      = ZERO;
            if (botZero) yc[NY - 1] = ZERO;

            const int ty  = t - 1;             // local y-col index 0..2W+1
            const int wlA = ty >> 1;           // output col with dj = ty&1
            const int djA = ty & 1;
#pragma unroll
            for (int rl = 0; rl < TILE_R; rl++) {
                // vertical reduction: V = sum_di w[di] * y[2rl+di]
                float4 V = ZERO;
                f4fma(V, wv0, yc[2*rl + 0]);
                f4fma(V, wv1, yc[2*rl + 1]);
                f4fma(V, wv1, yc[2*rl + 2]);
                f4fma(V, wv0, yc[2*rl + 3]);
                if (wlA < TILE_W) {            // dj = djA (0 or 1)
                    const float wA = (djA == 0) ? wv0 : wv1;
                    f4fma(acc[rl][wlA], wA, V);
                }
                if (wlA >= 1) {                // dj = djA + 2 (2 or 3)
                    const float wB = (djA == 0) ? wv1 : wv0;
                    f4fma(acc[rl][wlA - 1], wB, V);
                }
            }
        }
#pragma unroll
        for (int k = 0; k < NY; k++) cmPrev[k] = cm[k];
    }

    // Store 2x4 output pixels (float4 = 4 channels each)
#pragma unroll
    for (int rl = 0; rl < TILE_R; rl++) {
        const int oi = oi0 + rl;
#pragma unroll
        for (int wl = 0; wl < TILE_W; wl++) {
            const int oj = oj0 + wl;
            out[(((size_t)b * 56 + oi) * 56 + oj) * 32 + lane] = acc[rl][wl];
        }
    }
}

extern "C" void kernel_launch(void* const* d_in, const int* in_sizes, int n_in,
                              void* d_out, int out_size) {
    const float4* x = (const float4*)d_in[0];   // (32,112,112,128) f32
    // d_in[1] = blur kernel (ignored: baked into (1,3,3,1)/8 weights)
    float4* out = (float4*)d_out;               // (32,56,56,128) f32

    const int tiles = 32 * TI_N * TJ_N;         // 12544
    dim3 block(32, 8);                          // 32 channel lanes x 8 tiles
    dim3 grid((tiles + 7) / 8);                 // 1568 blocks
    mbp_kernel<<<grid, block>>>(x, out);
}